// round 16
// baseline (speedup 1.0000x reference)
#include <cuda_runtime.h>

// NeighborlistForInference: brute-force N^2 upper-triangular pair list.
//
// Output layout (fp32, 6*P elements, P = n(n-1)/2):
//   [0   ,  P) : i index per pair (-1 if out of cutoff)
//   [P   , 2P) : j index per pair (-1)
//   [2P  , 3P) : d_ij (0)
//   [3P  , 6P) : r_ij row-major [P,3] (0)
//
// Round-16 = champion config (ITERS=4, cheap conservative vote, exact slow
// path, 2x STG.128 fast store) + SoA position tables:
//  * a tiny transpose kernel writes pos into __device__ px/py/pz once per
//    launch; hot-loop loads then have 4B lane stride -> 1 L1 wavefront per
//    LDG instead of 3 (9 -> 3 load wavefronts per warp-iteration).
//  * ITERS=4 (128 pairs/warp) measured best: more concurrent warps = better
//    DRAM drain (ITERS 4/8/16 -> 61.5/61.9/64.2us).
//  * stored bits identical to previous rounds (rel_err 3e-8).

#ifndef NL_CUTOFF
#define NL_CUTOFF 0.5f
#endif

#define BLOCK_THREADS  256
#define ITERS          4
#define PAIRS_PER_WARP (32 * ITERS)   // 128
#define MAX_N          16384

__device__ float g_px[MAX_N];
__device__ float g_py[MAX_N];
__device__ float g_pz[MAX_N];

__global__ void transpose_pos_kernel(const float* __restrict__ pos, int n)
{
    const int k = blockIdx.x * blockDim.x + threadIdx.x;
    if (k < n) {
        g_px[k] = pos[3 * k + 0];
        g_py[k] = pos[3 * k + 1];
        g_pz[k] = pos[3 * k + 2];
    }
}

__device__ __forceinline__ int tri_start(int i, int n) {
    return (i * (2 * n - i - 1)) >> 1;     // row start, max ~36M fits int32
}

__device__ __forceinline__ int tri_row(int p, int n) {
    const int a = 2 * n - 1;
    const int disc = a * a - 8 * p;
    int i = (int)(0.5f * ((float)a - sqrtf((float)disc)));
    if (i < 0) i = 0;
    if (i > n - 2) i = n - 2;
    while (p < tri_start(i, n)) --i;
    while (i < n - 2 && p >= tri_start(i + 1, n)) ++i;
    return i;
}

__global__ __launch_bounds__(BLOCK_THREADS)
void neighborlist_kernel(const float* __restrict__ box,
                         const int*   __restrict__ is_periodic,
                         float* __restrict__ out_i,
                         float* __restrict__ out_j,
                         float* __restrict__ out_d,
                         float* __restrict__ out_r,
                         int n, int P)
{
    const int warp = (blockIdx.x * BLOCK_THREADS + threadIdx.x) >> 5;
    const int lane = threadIdx.x & 31;
    const int wb   = warp * PAIRS_PER_WARP;
    if (wb >= P) return;

    // ---- per-lane triangular index at first pair (clamped for tail lanes)
    int p  = wb + lane;
    const int pc = min(p, P - 1);
    int i  = tri_row(pc, n);
    int rs = tri_start(i, n);
    int j  = i + 1 + (pc - rs);

    const float Lx = box[0], Ly = box[4], Lz = box[8];
    const float hx = 0.5f * Lx, hy = 0.5f * Ly, hz = 0.5f * Lz;
    const int per = *is_periodic;

    // cheap-mask effective box lengths: +INF disables wrapping when per==0
    const float INFF = __int_as_float(0x7f800000);
    const float LxE = per ? Lx : INFF;
    const float LyE = per ? Ly : INFF;
    const float LzE = per ? Lz : INFF;

    // exact mask threshold: largest s with fl(sqrt(s)) <= 0.5
    const float SMAX   = __uint_as_float(0x3E800001u);
    const float SCHEAP = 0.2503f;          // SMAX + conservative margin

    float xi = g_px[i], yi = g_py[i], zi = g_pz[i];

    // ---- fast-path cooperative store plan:
    // lanes 0-7 -> i block, 8-15 -> j block, 16-23 -> d block (16B each),
    // lanes 0-23 also cover the 384B r block (16B each).
    float* ijd_ptr;
    {
        float* sb = (lane < 8) ? out_i : (lane < 16) ? out_j : out_d;
        ijd_ptr = sb + wb + 4 * (lane & 7);
    }
    float* r_ptr = out_r + 3 * wb + 4 * lane;
    const float4 cval = (lane < 16) ? make_float4(-1.f, -1.f, -1.f, -1.f)
                                    : make_float4(0.f, 0.f, 0.f, 0.f);
    const float4 zero4 = make_float4(0.f, 0.f, 0.f, 0.f);
    const bool storer = (lane < 24);

    if (wb + PAIRS_PER_WARP <= P) {
        // ================= full warp: no bounds checks =================
        #pragma unroll
        for (int m = 0; m < ITERS; ++m) {
            if (m) {
                p += 32; j += 32;
                if (j >= n) {               // row crossing(s)
                    do {
                        rs += n - 1 - i;
                        ++i;
                        j = i + 1 + (p - rs);
                    } while (j >= n);
                    xi = g_px[i]; yi = g_py[i]; zi = g_pz[i];
                }
            }

            // SoA loads: 4B lane stride -> 1 L1 wavefront per LDG
            float dx = xi - g_px[j];
            float dy = yi - g_py[j];
            float dz = zi - g_pz[j];

            // conservative min-image magnitude (never under-counts a hit)
            const float ax = fabsf(dx), mx = fminf(ax, LxE - ax);
            const float ay = fabsf(dy), my = fminf(ay, LyE - ay);
            const float az = fabsf(dz), mz = fminf(az, LzE - az);
            const float sc = mx * mx + my * my + mz * mz;

            if (!__any_sync(0xffffffffu, sc <= SCHEAP)) {
                // all 32 pairs clearly out: constant outputs, 2 x STG.128
                if (storer) {
                    __stcs((float4*)ijd_ptr, cval);
                    __stcs((float4*)r_ptr,   zero4);
                }
            } else {
                // exact path (bit-identical to previous rounds)
                if (per) {
                    float tx = dx + hx; tx = (tx >= Lx) ? tx - Lx : tx; tx = (tx < 0.0f) ? tx + Lx : tx; dx = tx - hx;
                    float ty = dy + hy; ty = (ty >= Ly) ? ty - Ly : ty; ty = (ty < 0.0f) ? ty + Ly : ty; dy = ty - hy;
                    float tz = dz + hz; tz = (tz >= Lz) ? tz - Lz : tz; tz = (tz < 0.0f) ? tz + Lz : tz; dz = tz - hz;
                }
                const float s  = dx * dx + dy * dy + dz * dz;
                const bool  in = (s <= SMAX);     // == (sqrtf(s) <= 0.5f)
                const float d  = sqrtf(s);        // IEEE
                __stcs(out_i + p, in ? (float)i : -1.0f);
                __stcs(out_j + p, in ? (float)j : -1.0f);
                __stcs(out_d + p, in ? d        :  0.0f);
                float* rb = out_r + 3 * p;
                __stcs(rb + 0, in ? dx : 0.0f);
                __stcs(rb + 1, in ? dy : 0.0f);
                __stcs(rb + 2, in ? dz : 0.0f);
            }

            ijd_ptr += 32;                  // +128B per iteration
            r_ptr   += 96;                  // +384B per iteration
        }
    } else {
        // ============ partial (last) warp: guarded scalar loop ============
        #pragma unroll 1
        for (int m = 0; m < ITERS; ++m) {
            if (m) {
                p += 32; j += 32;
                if (j >= n && p < P) {
                    do {
                        rs += n - 1 - i;
                        ++i;
                        j = i + 1 + (p - rs);
                    } while (j >= n);
                    xi = g_px[i]; yi = g_py[i]; zi = g_pz[i];
                }
            }
            if (p < P) {
                float dx = xi - g_px[j];
                float dy = yi - g_py[j];
                float dz = zi - g_pz[j];
                if (per) {
                    float tx = dx + hx; tx = (tx >= Lx) ? tx - Lx : tx; tx = (tx < 0.0f) ? tx + Lx : tx; dx = tx - hx;
                    float ty = dy + hy; ty = (ty >= Ly) ? ty - Ly : ty; ty = (ty < 0.0f) ? ty + Ly : ty; dy = ty - hy;
                    float tz = dz + hz; tz = (tz >= Lz) ? tz - Lz : tz; tz = (tz < 0.0f) ? tz + Lz : tz; dz = tz - hz;
                }
                const float s  = dx * dx + dy * dy + dz * dz;
                const bool  in = (s <= SMAX);
                const float d  = sqrtf(s);
                __stcs(out_i + p, in ? (float)i : -1.0f);
                __stcs(out_j + p, in ? (float)j : -1.0f);
                __stcs(out_d + p, in ? d        :  0.0f);
                float* rb = out_r + 3 * p;
                __stcs(rb + 0, in ? dx : 0.0f);
                __stcs(rb + 1, in ? dy : 0.0f);
                __stcs(rb + 2, in ? dz : 0.0f);
            }
        }
    }
}

// Fallback (n > MAX_N): AoS loads, same math. Not expected to run for this
// dataset (n = 6000), kept for safety.
__global__ __launch_bounds__(BLOCK_THREADS)
void neighborlist_kernel_aos(const float* __restrict__ pos,
                             const float* __restrict__ box,
                             const int*   __restrict__ is_periodic,
                             float* __restrict__ out_i,
                             float* __restrict__ out_j,
                             float* __restrict__ out_d,
                             float* __restrict__ out_r,
                             int n, int P)
{
    const int warp = (blockIdx.x * BLOCK_THREADS + threadIdx.x) >> 5;
    const int lane = threadIdx.x & 31;
    int p = warp * PAIRS_PER_WARP + lane;
    if (warp * PAIRS_PER_WARP >= P) return;

    const int pc = min(p, P - 1);
    int i  = tri_row(pc, n);
    int rs = tri_start(i, n);
    int j  = i + 1 + (pc - rs);

    const float Lx = box[0], Ly = box[4], Lz = box[8];
    const float hx = 0.5f * Lx, hy = 0.5f * Ly, hz = 0.5f * Lz;
    const int per = *is_periodic;
    const float SMAX = __uint_as_float(0x3E800001u);

    float xi = pos[3 * i + 0], yi = pos[3 * i + 1], zi = pos[3 * i + 2];

    #pragma unroll 1
    for (int m = 0; m < ITERS; ++m) {
        if (m) {
            p += 32; j += 32;
            if (j >= n && p < P) {
                do { rs += n - 1 - i; ++i; j = i + 1 + (p - rs); } while (j >= n);
                xi = pos[3 * i + 0]; yi = pos[3 * i + 1]; zi = pos[3 * i + 2];
            }
        }
        if (p < P) {
            float dx = xi - pos[3 * j + 0];
            float dy = yi - pos[3 * j + 1];
            float dz = zi - pos[3 * j + 2];
            if (per) {
                float tx = dx + hx; tx = (tx >= Lx) ? tx - Lx : tx; tx = (tx < 0.0f) ? tx + Lx : tx; dx = tx - hx;
                float ty = dy + hy; ty = (ty >= Ly) ? ty - Ly : ty; ty = (ty < 0.0f) ? ty + Ly : ty; dy = ty - hy;
                float tz = dz + hz; tz = (tz >= Lz) ? tz - Lz : tz; tz = (tz < 0.0f) ? tz + Lz : tz; dz = tz - hz;
            }
            const float s  = dx * dx + dy * dy + dz * dz;
            const bool  in = (s <= SMAX);
            const float d  = sqrtf(s);
            __stcs(out_i + p, in ? (float)i : -1.0f);
            __stcs(out_j + p, in ? (float)j : -1.0f);
            __stcs(out_d + p, in ? d        :  0.0f);
            float* rb = out_r + 3 * p;
            __stcs(rb + 0, in ? dx : 0.0f);
            __stcs(rb + 1, in ? dy : 0.0f);
            __stcs(rb + 2, in ? dz : 0.0f);
        }
    }
}

extern "C" void kernel_launch(void* const* d_in, const int* in_sizes, int n_in,
                              void* d_out, int out_size)
{
    const float* pos   = (const float*)d_in[0];
    const float* box   = (const float*)d_in[1];
    const int*   isper = (const int*)d_in[2];
    float*       out   = (float*)d_out;

    const int n = in_sizes[0] / 3;
    const int P = (int)((long long)n * (n - 1) / 2);   // 17,997,000 for n=6000

    const int pairs_per_block = (BLOCK_THREADS / 32) * PAIRS_PER_WARP;  // 1024
    const int grid = (P + pairs_per_block - 1) / pairs_per_block;

    if (n <= MAX_N) {
        transpose_pos_kernel<<<(n + 255) / 256, 256>>>(pos, n);
        neighborlist_kernel<<<grid, BLOCK_THREADS>>>(box, isper,
                                                     out,
                                                     out + P,
                                                     out + 2 * (size_t)P,
                                                     out + 3 * (size_t)P,
                                                     n, P);
    } else {
        neighborlist_kernel_aos<<<grid, BLOCK_THREADS>>>(pos, box, isper,
                                                         out,
                                                         out + P,
                                                         out + 2 * (size_t)P,
                                                         out + 3 * (size_t)P,
                                                         n, P);
    }
}

// round 17
// speedup vs baseline: 1.0420x; 1.0420x over previous
#include <cuda_runtime.h>

// NeighborlistForInference: brute-force N^2 upper-triangular pair list.
//
// Output layout (fp32, 6*P elements, P = n(n-1)/2):
//   [0   ,  P) : i index per pair (-1 if out of cutoff)
//   [P   , 2P) : j index per pair (-1)
//   [2P  , 3P) : d_ij (0)
//   [3P  , 6P) : r_ij row-major [P,3] (0)
//
// Round-17 = consolidated best-of-all-rounds, single launch:
//  * AoS loads (no transpose kernel: R16 showed +3.7us launch overhead for
//    -0.4us kernel gain).
//  * ITERS=4 / 128 pairs per warp (measured best DRAM drain: 4/8/16 ->
//    61.5/61.9/64.2us).
//  * warp vote on CONSERVATIVE cheap mask m=min(|dx|,L-|dx|), sc<=0.2503;
//    cannot miss a true hit; warps failing the vote take the exact path.
//  * exact path: t-form wrap (bit-identical to jnp.remainder for r in
//    (-L,L)), mask s<=0x3E800001 == (IEEE sqrtf(s)<=0.5f), IEEE sqrt.
//  * fast store: two predicated STG.128 (.cs) on lanes 0..23 covering the
//    three 128B i/j/d blocks + 384B zero r block.
//  * 512-thread blocks: halves block count; steady state unchanged.
// Kernel is at the HBM write wall (~7.1 TB/s payload, DRAM 78%).

#ifndef NL_CUTOFF
#define NL_CUTOFF 0.5f
#endif

#define BLOCK_THREADS  512
#define ITERS          4
#define PAIRS_PER_WARP (32 * ITERS)   // 128

__device__ __forceinline__ int tri_start(int i, int n) {
    return (i * (2 * n - i - 1)) >> 1;     // row start, max ~36M fits int32
}

__device__ __forceinline__ int tri_row(int p, int n) {
    const int a = 2 * n - 1;
    const int disc = a * a - 8 * p;
    int i = (int)(0.5f * ((float)a - sqrtf((float)disc)));
    if (i < 0) i = 0;
    if (i > n - 2) i = n - 2;
    while (p < tri_start(i, n)) --i;
    while (i < n - 2 && p >= tri_start(i + 1, n)) ++i;
    return i;
}

__global__ __launch_bounds__(BLOCK_THREADS)
void neighborlist_kernel(const float* __restrict__ pos,
                         const float* __restrict__ box,
                         const int*   __restrict__ is_periodic,
                         float* __restrict__ out_i,
                         float* __restrict__ out_j,
                         float* __restrict__ out_d,
                         float* __restrict__ out_r,
                         int n, int P)
{
    const int warp = (blockIdx.x * BLOCK_THREADS + threadIdx.x) >> 5;
    const int lane = threadIdx.x & 31;
    const int wb   = warp * PAIRS_PER_WARP;
    if (wb >= P) return;

    // ---- per-lane triangular index at first pair (clamped for tail lanes)
    int p  = wb + lane;
    const int pc = min(p, P - 1);
    int i  = tri_row(pc, n);
    int rs = tri_start(i, n);
    int j  = i + 1 + (pc - rs);

    const float Lx = box[0], Ly = box[4], Lz = box[8];
    const float hx = 0.5f * Lx, hy = 0.5f * Ly, hz = 0.5f * Lz;
    const int per = *is_periodic;

    // cheap-mask effective box lengths: +INF disables wrapping when per==0
    const float INFF = __int_as_float(0x7f800000);
    const float LxE = per ? Lx : INFF;
    const float LyE = per ? Ly : INFF;
    const float LzE = per ? Lz : INFF;

    // exact mask threshold: largest s with fl(sqrt(s)) <= 0.5
    const float SMAX   = __uint_as_float(0x3E800001u);
    const float SCHEAP = 0.2503f;          // SMAX + conservative margin

    float xi = pos[3 * i + 0], yi = pos[3 * i + 1], zi = pos[3 * i + 2];

    // ---- fast-path cooperative store plan:
    // lanes 0-7 -> i block, 8-15 -> j block, 16-23 -> d block (16B each),
    // lanes 0-23 also cover the 384B r block (16B each).
    float* ijd_ptr;
    {
        float* sb = (lane < 8) ? out_i : (lane < 16) ? out_j : out_d;
        ijd_ptr = sb + wb + 4 * (lane & 7);
    }
    float* r_ptr = out_r + 3 * wb + 4 * lane;
    const float4 cval = (lane < 16) ? make_float4(-1.f, -1.f, -1.f, -1.f)
                                    : make_float4(0.f, 0.f, 0.f, 0.f);
    const float4 zero4 = make_float4(0.f, 0.f, 0.f, 0.f);
    const bool storer = (lane < 24);

    if (wb + PAIRS_PER_WARP <= P) {
        // ================= full warp: no bounds checks =================
        #pragma unroll
        for (int m = 0; m < ITERS; ++m) {
            if (m) {
                p += 32; j += 32;
                if (j >= n) {               // row crossing(s)
                    do {
                        rs += n - 1 - i;
                        ++i;
                        j = i + 1 + (p - rs);
                    } while (j >= n);
                    xi = pos[3 * i + 0]; yi = pos[3 * i + 1]; zi = pos[3 * i + 2];
                }
            }

            float dx = xi - pos[3 * j + 0];
            float dy = yi - pos[3 * j + 1];
            float dz = zi - pos[3 * j + 2];

            // conservative min-image magnitude (never under-counts a hit)
            const float ax = fabsf(dx), mx = fminf(ax, LxE - ax);
            const float ay = fabsf(dy), my = fminf(ay, LyE - ay);
            const float az = fabsf(dz), mz = fminf(az, LzE - az);
            const float sc = mx * mx + my * my + mz * mz;

            if (!__any_sync(0xffffffffu, sc <= SCHEAP)) {
                // all 32 pairs clearly out: constant outputs, 2 x STG.128
                if (storer) {
                    __stcs((float4*)ijd_ptr, cval);
                    __stcs((float4*)r_ptr,   zero4);
                }
            } else {
                // exact path (bit-identical to previous rounds)
                if (per) {
                    float tx = dx + hx; tx = (tx >= Lx) ? tx - Lx : tx; tx = (tx < 0.0f) ? tx + Lx : tx; dx = tx - hx;
                    float ty = dy + hy; ty = (ty >= Ly) ? ty - Ly : ty; ty = (ty < 0.0f) ? ty + Ly : ty; dy = ty - hy;
                    float tz = dz + hz; tz = (tz >= Lz) ? tz - Lz : tz; tz = (tz < 0.0f) ? tz + Lz : tz; dz = tz - hz;
                }
                const float s  = dx * dx + dy * dy + dz * dz;
                const bool  in = (s <= SMAX);     // == (sqrtf(s) <= 0.5f)
                const float d  = sqrtf(s);        // IEEE
                __stcs(out_i + p, in ? (float)i : -1.0f);
                __stcs(out_j + p, in ? (float)j : -1.0f);
                __stcs(out_d + p, in ? d        :  0.0f);
                float* rb = out_r + 3 * p;
                __stcs(rb + 0, in ? dx : 0.0f);
                __stcs(rb + 1, in ? dy : 0.0f);
                __stcs(rb + 2, in ? dz : 0.0f);
            }

            ijd_ptr += 32;                  // +128B per iteration
            r_ptr   += 96;                  // +384B per iteration
        }
    } else {
        // ============ partial (last) warp: guarded scalar loop ============
        #pragma unroll 1
        for (int m = 0; m < ITERS; ++m) {
            if (m) {
                p += 32; j += 32;
                if (j >= n && p < P) {
                    do {
                        rs += n - 1 - i;
                        ++i;
                        j = i + 1 + (p - rs);
                    } while (j >= n);
                    xi = pos[3 * i + 0]; yi = pos[3 * i + 1]; zi = pos[3 * i + 2];
                }
            }
            if (p < P) {
                float dx = xi - pos[3 * j + 0];
                float dy = yi - pos[3 * j + 1];
                float dz = zi - pos[3 * j + 2];
                if (per) {
                    float tx = dx + hx; tx = (tx >= Lx) ? tx - Lx : tx; tx = (tx < 0.0f) ? tx + Lx : tx; dx = tx - hx;
                    float ty = dy + hy; ty = (ty >= Ly) ? ty - Ly : ty; ty = (ty < 0.0f) ? ty + Ly : ty; dy = ty - hy;
                    float tz = dz + hz; tz = (tz >= Lz) ? tz - Lz : tz; tz = (tz < 0.0f) ? tz + Lz : tz; dz = tz - hz;
                }
                const float s  = dx * dx + dy * dy + dz * dz;
                const bool  in = (s <= SMAX);
                const float d  = sqrtf(s);
                __stcs(out_i + p, in ? (float)i : -1.0f);
                __stcs(out_j + p, in ? (float)j : -1.0f);
                __stcs(out_d + p, in ? d        :  0.0f);
                float* rb = out_r + 3 * p;
                __stcs(rb + 0, in ? dx : 0.0f);
                __stcs(rb + 1, in ? dy : 0.0f);
                __stcs(rb + 2, in ? dz : 0.0f);
            }
        }
    }
}

extern "C" void kernel_launch(void* const* d_in, const int* in_sizes, int n_in,
                              void* d_out, int out_size)
{
    const float* pos   = (const float*)d_in[0];
    const float* box   = (const float*)d_in[1];
    const int*   isper = (const int*)d_in[2];
    float*       out   = (float*)d_out;

    const int n = in_sizes[0] / 3;
    const int P = (int)((long long)n * (n - 1) / 2);   // 17,997,000 for n=6000

    const int pairs_per_block = (BLOCK_THREADS / 32) * PAIRS_PER_WARP;  // 2048
    const int grid = (P + pairs_per_block - 1) / pairs_per_block;
    neighborlist_kernel<<<grid, BLOCK_THREADS>>>(pos, box, isper,
                                                 out,
                                                 out + P,
                                                 out + 2 * (size_t)P,
                                                 out + 3 * (size_t)P,
                                                 n, P);
}